// round 15
// baseline (speedup 1.0000x reference)
#include <cuda_runtime.h>
#include <cuda_fp16.h>
#include <cstdint>
#include <math.h>

#define T_LEN 256
#define B_DIM 512
#define F_DIM 256
#define H_DIM 512
#define P_INT 12
#define KTOT  768
#define NG    2048
#define NW    22
#define XTOT  (T_LEN * B_DIM * F_DIM)

// ---------------- GEMM tiling ----------------
#define BM 128
#define BN 128
#define BK 64
#define STG 3
#define NCH (KTOT / BK)

#define A_SZ (BM * BK * 2)
#define B_SZ (BN * BK * 2)
#define SMEM_BYTES (STG * (A_SZ + B_SZ))  // 96 KB

#define WAVE_ROWS (P_INT * B_DIM)
#define WAVE_S ((size_t)WAVE_ROWS * NG)
#define NMT_MAX 48

// tasks: 21 full waves (768 gemm + 768 pw = 1536); pruned last wave: 112 gemm + 64 pw
#define FULL_TASKS (21 * 1536)
#define LAST_GEMM 112
#define LAST_TASKS (LAST_GEMM + 64)
#define TOTAL_TASKS (FULL_TASKS + LAST_TASKS)

__device__ __constant__ int c_lastmt[7] = {0, 4, 8, 12, 13, 14, 15};

// ---------------- static device scratch ----------------
__device__ __half d_Wh[NG * KTOT];
__device__ float  d_Bcat[NG];
__device__ __half d_Xh[XTOT];
__device__ __half d_Hh[P_INT * B_DIM * H_DIM];
__device__ __half d_Sbuf[2 * WAVE_S];
__device__ float  d_Vbuf[2 * P_INT * H_DIM];
__device__ int    d_gemmdone[NMT_MAX];
__device__ int    d_pwdone[NMT_MAX];
__device__ int    d_vflag[P_INT];
__device__ int    d_qhead;

// ---------------- helpers ----------------
__device__ __forceinline__ uint32_t smem_u32(const void* p) {
    uint32_t a;
    asm("{ .reg .u64 t; cvta.to.shared.u64 t, %1; cvt.u32.u64 %0, t; }" : "=r"(a) : "l"(p));
    return a;
}
__device__ __forceinline__ void cpasync16(uint32_t dst, const void* src) {
    asm volatile("cp.async.cg.shared.global [%0], [%1], 16;"
                 :: "r"(dst), "l"(__cvta_generic_to_global(src)) : "memory");
}
__device__ __forceinline__ void ldm4(uint32_t* r, uint32_t addr) {
    asm volatile("ldmatrix.sync.aligned.m8n8.x4.shared.b16 {%0,%1,%2,%3}, [%4];"
                 : "=r"(r[0]), "=r"(r[1]), "=r"(r[2]), "=r"(r[3]) : "r"(addr));
}
__device__ __forceinline__ void stm4(uint32_t addr, uint32_t r0, uint32_t r1,
                                     uint32_t r2, uint32_t r3) {
    asm volatile("stmatrix.sync.aligned.m8n8.x4.shared.b16 [%0], {%1,%2,%3,%4};"
                 :: "r"(addr), "r"(r0), "r"(r1), "r"(r2), "r"(r3) : "memory");
}
__device__ __forceinline__ void mma16816(float* d, const uint32_t* a, uint32_t b0, uint32_t b1) {
    asm volatile(
        "mma.sync.aligned.m16n8k16.row.col.f32.f16.f16.f32 "
        "{%0,%1,%2,%3}, {%4,%5,%6,%7}, {%8,%9}, {%0,%1,%2,%3};"
        : "+f"(d[0]), "+f"(d[1]), "+f"(d[2]), "+f"(d[3])
        : "r"(a[0]), "r"(a[1]), "r"(a[2]), "r"(a[3]), "r"(b0), "r"(b1));
}
__device__ __forceinline__ int ld_acq(const int* p) {
    int v;
    asm volatile("ld.acquire.gpu.s32 %0, [%1];" : "=r"(v) : "l"(p) : "memory");
    return v;
}
__device__ __forceinline__ void spin_hot(const int* p, int tgt) {
    while (ld_acq(p) < tgt) { }
}
__device__ __forceinline__ void spin_bk(const int* p, int tgt) {
    if (ld_acq(p) >= tgt) return;
    while (ld_acq(p) < tgt) __nanosleep(64);
}
__device__ __forceinline__ void done_release(int* p) {
    asm volatile("red.release.gpu.global.add.s32 [%0], %1;"
                 :: "l"(__cvta_generic_to_global(p)), "r"(1) : "memory");
}
__device__ __forceinline__ float tanh_fast(float x) {
    float y;
    asm("tanh.approx.f32 %0, %1;" : "=f"(y) : "f"(x));
    return y;
}

// ---------------- fused prologue: convert x, pack W/b, init state ----------------
__global__ void prologue_kernel(const float* __restrict__ x,
                                const float* __restrict__ Wf, const float* __restrict__ bf,
                                const float* __restrict__ Wi, const float* __restrict__ bi,
                                const float* __restrict__ Wo, const float* __restrict__ bo,
                                const float* __restrict__ Wg, const float* __restrict__ bg) {
    int idx = blockIdx.x * blockDim.x + threadIdx.x;
    d_Xh[idx] = __float2half(x[idx]);                     // grid sized to XTOT
    if (idx < NG * KTOT) {
        int n = idx / KTOT;
        int k = idx % KTOT;
        int g = n >> 9, h = n & 511;
        const float* W = (g == 0) ? Wf : (g == 1) ? Wi : (g == 2) ? Wo : Wg;
        d_Wh[idx] = __float2half(W[k * H_DIM + h]);
    }
    if (idx < NG) {
        int g = idx / H_DIM, h = idx % H_DIM;
        const float* bb = (g == 0) ? bf : (g == 1) ? bi : (g == 2) ? bo : bg;
        d_Bcat[idx] = bb[h];
    }
    if (idx < P_INT * B_DIM * H_DIM) d_Hh[idx] = __float2half(0.0f);
    if (idx < NMT_MAX) { d_gemmdone[idx] = 0; d_pwdone[idx] = 0; }
    if (idx < P_INT) d_vflag[idx] = 0;
    if (idx == 0) d_qhead = 0;
}

// ---------------- stage loader ----------------
__device__ __forceinline__ void load_stage(uint32_t sa, uint32_t sbB, int tid, int ch,
                                           const __half* Xb, const __half* Hb, const __half* Wb) {
    const int k0 = ch * BK;
    const __half* asrc;
    int astride;
    if (k0 < F_DIM) { asrc = Xb + k0;           astride = F_DIM; }
    else            { asrc = Hb + (k0 - F_DIM); astride = H_DIM; }
    #pragma unroll
    for (int i = 0; i < 4; i++) {
        int cell = tid + i * 256;
        int r = cell >> 3, c = cell & 7;
        cpasync16(sa + r * 128 + ((c ^ (r & 7)) * 16),
                  asrc + (size_t)r * astride + c * 8);
    }
    #pragma unroll
    for (int i = 0; i < 4; i++) {
        int cell = tid + i * 256;
        int r = cell >> 3, c = cell & 7;
        cpasync16(sbB + r * 128 + ((c ^ (r & 7)) * 16),
                  Wb + (size_t)r * KTOT + k0 + c * 8);
    }
}

// ---------------- warp softmax over 512 values (16 per lane) ----------------
__device__ __forceinline__ void softmax16(float* s) {
    float mx = -1e30f;
    #pragma unroll
    for (int q = 0; q < 16; q++) mx = fmaxf(mx, s[q]);
    #pragma unroll
    for (int o = 16; o > 0; o >>= 1) mx = fmaxf(mx, __shfl_xor_sync(0xffffffffu, mx, o));
    float sum = 0.0f;
    #pragma unroll
    for (int q = 0; q < 16; q++) { s[q] = __expf(s[q] - mx); sum += s[q]; }
    #pragma unroll
    for (int o = 16; o > 0; o >>= 1) sum += __shfl_xor_sync(0xffffffffu, sum, o);
    const float inv = 1.0f / sum;
    #pragma unroll
    for (int q = 0; q < 16; q++) s[q] *= inv;
}
// element q of lane l <-> column (q>>1)*64 + l*2 + (q&1)
__device__ __forceinline__ void load_gate16(const __half2* base, int l, float* s) {
    #pragma unroll
    for (int q2 = 0; q2 < 8; q2++) {
        float2 v = __half22float2(base[q2 * 32 + l]);
        s[2 * q2] = v.x;
        s[2 * q2 + 1] = v.y;
    }
}

// ---------------- persistent fused kernel ----------------
__global__ void __launch_bounds__(256, 2) persist(float* __restrict__ out) {
    extern __shared__ char smem[];
    const int G = gridDim.x;
    const int tid = threadIdx.x;

    if ((int)blockIdx.x == G - 1) {
        // ===== chain CTA: one warp, register-resident v across ALL waves =====
        if (tid >= 32) return;
        const int l = tid;
        float v[16];
        #pragma unroll
        for (int q = 0; q < 16; q++) v[q] = 0.0f;

        for (int w = 0; w < NW; w++) {
            const int t0 = w * P_INT;
            const int ns = (T_LEN - t0 < P_INT) ? (T_LEN - t0) : P_INT;
            const __half2* Sb2 = (const __half2*)(d_Sbuf + (size_t)(w & 1) * WAVE_S);
            float* Vb = d_Vbuf + (w & 1) * P_INT * H_DIM;
            for (int j = 0; j < ns; j++) {
                if (w >= 2 && l < 4) spin_hot(&d_pwdone[4 * j + l], 16 * (w - 1));
                __syncwarp();
                #pragma unroll
                for (int q2 = 0; q2 < 8; q2++)
                    *(float2*)(Vb + j * H_DIM + q2 * 64 + l * 2) =
                        make_float2(v[2 * q2], v[2 * q2 + 1]);
                __threadfence();
                __syncwarp();
                if (l == 0)
                    asm volatile("st.release.gpu.s32 [%0], %1;"
                                 :: "l"(d_vflag + j), "r"(w + 1) : "memory");
                spin_hot(&d_gemmdone[4 * j], 16 * (w + 1));
                const int r = (t0 + j + 1) % P_INT;
                const __half2* S = Sb2 + (((size_t)(j * B_DIM + r) * NG) >> 1);
                float sf[16], si[16], sg[16];
                load_gate16(S, l, sf);
                load_gate16(S + (H_DIM >> 1), l, si);
                load_gate16(S + ((3 * H_DIM) >> 1), l, sg);
                softmax16(sf);
                softmax16(si);
                #pragma unroll
                for (int q = 0; q < 16; q++)
                    v[q] = tanh_fast(sf[q] * v[q] + si[q] * tanh_fast(sg[q]));
            }
        }
        return;
    }

    // ===== worker CTA: global task queue =====
    __shared__ int s_task;
    const uint32_t sb = smem_u32(smem);
    const int wid = tid >> 5;
    const int l   = tid & 31;
    const int wm = (wid >> 2) * 64;
    const int wn = (wid & 3) * 32;
    const int lrow = l & 15;
    const int lk   = l >> 4;

    uint32_t sA[STG], sBs[STG];
    #pragma unroll
    for (int s = 0; s < STG; s++) {
        sA[s]  = sb + s * (A_SZ + B_SZ);
        sBs[s] = sA[s] + A_SZ;
    }

    while (true) {
        __syncthreads();
        if (tid == 0) s_task = atomicAdd(&d_qhead, 1);
        __syncthreads();
        const int task = s_task;
        if (task >= TOTAL_TASKS) break;

        int w, r, ns, ntile;
        bool is_gemm;
        int mtile = 0, n0 = 0, pwb = 0;
        if (task < FULL_TASKS) {
            w = task / 1536; r = task % 1536; ns = 12; ntile = 768;
            if (r < ntile) {
                is_gemm = true;
                const int grp = ns * 16;
                mtile = ((r % grp) >> 4) * 4 + r / grp;
                n0 = (r & 15) * BN;
            } else {
                is_gemm = false;
                pwb = r - ntile;
            }
        } else {
            w = 21; r = task - FULL_TASKS; ns = 4;
            if (r < LAST_GEMM) {
                is_gemm = true;
                mtile = c_lastmt[r >> 4];
                n0 = (r & 15) * BN;
            } else {
                is_gemm = false;
                pwb = 192 + (r - LAST_GEMM);   // only j==3 blocks
            }
        }
        const int t0 = w * P_INT;
        __half* Sb = d_Sbuf + (size_t)(w & 1) * WAVE_S;

        if (is_gemm) {
            const int m0 = mtile * BM;
            const __half* Xb = d_Xh + ((size_t)t0 * B_DIM + m0) * F_DIM;
            const __half* Hb = d_Hh + (size_t)m0 * H_DIM;
            const __half* Wb = d_Wh + (size_t)n0 * KTOT;

            // wave 0: h ring is all zeros -> skip K-chunks 4..11 (exact)
            const int nch_t = (w == 0) ? 4 : NCH;

            float acc[4][4][4];
            #pragma unroll
            for (int i = 0; i < 4; i++)
                #pragma unroll
                for (int j = 0; j < 4; j++)
                    #pragma unroll
                    for (int q = 0; q < 4; q++) acc[i][j][q] = 0.0f;

            #pragma unroll
            for (int c = 0; c < STG - 1; c++) {
                load_stage(sA[c], sBs[c], tid, c, Xb, Hb, Wb);
                asm volatile("cp.async.commit_group;" ::: "memory");
            }

            for (int ch = 0; ch < nch_t; ch++) {
                asm volatile("cp.async.wait_group 1;" ::: "memory");
                __syncthreads();
                const int cl = ch + STG - 1;
                if (cl == 4)
                    spin_bk(&d_pwdone[mtile], 16 * w);
                if (cl < nch_t)
                    load_stage(sA[cl % STG], sBs[cl % STG], tid, cl, Xb, Hb, Wb);
                asm volatile("cp.async.commit_group;" ::: "memory");

                const int s = ch % STG;
                #pragma unroll
                for (int kk = 0; kk < BK / 16; kk++) {
                    uint32_t af[4][4], bfr[2][4];
                    #pragma unroll
                    for (int mi = 0; mi < 4; mi++) {
                        int rr = wm + mi * 16 + lrow;
                        int cc = kk * 2 + lk;
                        ldm4(af[mi], sA[s] + rr * 128 + ((cc ^ (rr & 7)) * 16));
                    }
                    #pragma unroll
                    for (int bj = 0; bj < 2; bj++) {
                        int rr = wn + bj * 16 + lrow;
                        int cc = kk * 2 + lk;
                        ldm4(bfr[bj], sBs[s] + rr * 128 + ((cc ^ (rr & 7)) * 16));
                    }
                    #pragma unroll
                    for (int mi = 0; mi < 4; mi++)
                        #pragma unroll
                        for (int nj = 0; nj < 4; nj++)
                            mma16816(acc[mi][nj], af[mi],
                                     bfr[nj >> 1][nj & 1], bfr[nj >> 1][(nj & 1) + 2]);
                }
            }

            // ---- epilogue: bias (fp32) -> half2, stmatrix to swizzled smem stage,
            //      then fully coalesced 128B stores to Sbuf ----
            __syncthreads();   // all warps done reading smem stages
            #pragma unroll
            for (int mi = 0; mi < 4; mi++) {
                #pragma unroll
                for (int p = 0; p < 2; p++) {
                    uint32_t regs[4];
                    #pragma unroll
                    for (int q = 0; q < 2; q++) {
                        const int nj = 2 * p + q;
                        const int n = n0 + wn + nj * 8 + (l & 3) * 2;
                        const float b0 = d_Bcat[n], b1 = d_Bcat[n + 1];
                        __half2 h01 = __floats2half2_rn(acc[mi][nj][0] + b0, acc[mi][nj][1] + b1);
                        __half2 h23 = __floats2half2_rn(acc[mi][nj][2] + b0, acc[mi][nj][3] + b1);
                        regs[2 * q]     = *(uint32_t*)&h01;
                        regs[2 * q + 1] = *(uint32_t*)&h23;
                    }
                    const int tilei = l >> 3, rin = l & 7;
                    const int row = wm + mi * 16 + (tilei & 1) * 8 + rin;
                    const int chunk = (wn >> 3) + 2 * p + (tilei >> 1);  // 16B chunk index
                    stm4(sb + row * 256 + (((uint32_t)(chunk ^ (row & 7))) << 4),
                         regs[0], regs[1], regs[2], regs[3]);
                }
            }
            __syncthreads();
            {
                const int row = tid >> 1, hf = tid & 1;
                uint4* dstp = (uint4*)(Sb + (size_t)(m0 + row) * NG + n0 + hf * 64);
                #pragma unroll
                for (int q = 0; q < 8; q++) {
                    const int sc = (hf * 8 + q) ^ (row & 7);
                    dstp[q] = *(const uint4*)(smem + row * 256 + sc * 16);
                }
            }
            __syncthreads();
            if (tid == 0) done_release(&d_gemmdone[mtile]);
        } else {
            // ---- pointwise block: 8 rows, warp per row ----
            const int b = pwb;
            const int mt = b >> 4;
            const int j  = b >> 6;
            if (tid == 0) spin_bk(&d_gemmdone[mt], 16 * (w + 1));
            __syncthreads();

            const int m = b * 8 + wid;
            const float* Vb = d_Vbuf + (w & 1) * P_INT * H_DIM;
            const __half2* S = (const __half2*)Sb + (((size_t)m * NG) >> 1);
            float sf[16], si[16], so[16], sg[16];
            load_gate16(S, l, sf);
            load_gate16(S + (H_DIM >> 1), l, si);
            load_gate16(S + ((2 * H_DIM) >> 1), l, so);
            load_gate16(S + ((3 * H_DIM) >> 1), l, sg);
            softmax16(sf);
            softmax16(si);
            softmax16(so);

            if (tid == 0) spin_bk(&d_vflag[j], w + 1);
            __syncthreads();

            __half2* Hh2 = (__half2*)d_Hh;
            const bool wout = (j == 3);
            #pragma unroll
            for (int q2 = 0; q2 < 8; q2++) {
                float2 vv = *(const float2*)(Vb + j * H_DIM + q2 * 64 + l * 2);
                float c0 = tanh_fast(sf[2 * q2] * vv.x + si[2 * q2] * tanh_fast(sg[2 * q2]));
                float c1 = tanh_fast(sf[2 * q2 + 1] * vv.y + si[2 * q2 + 1] * tanh_fast(sg[2 * q2 + 1]));
                float h0 = so[2 * q2] * c0;
                float h1 = so[2 * q2 + 1] * c1;
                Hh2[((size_t)m * H_DIM + q2 * 64 + l * 2) >> 1] = __floats2half2_rn(h0, h1);
                if (wout)
                    *(float2*)(out + (size_t)(m & 511) * H_DIM + q2 * 64 + l * 2) =
                        make_float2(h0, h1);
            }
            __syncthreads();
            if (tid == 0) done_release(&d_pwdone[mt]);
        }
    }
}

// ---------------- launch ----------------
extern "C" void kernel_launch(void* const* d_in, const int* in_sizes, int n_in,
                              void* d_out, int out_size) {
    const float* x  = (const float*)d_in[0];
    const float* Wf = (const float*)d_in[1];
    const float* bf = (const float*)d_in[2];
    const float* Wi = (const float*)d_in[3];
    const float* bi = (const float*)d_in[4];
    const float* Wo = (const float*)d_in[5];
    const float* bo = (const float*)d_in[6];
    const float* Wg = (const float*)d_in[7];
    const float* bg = (const float*)d_in[8];
    float* out = (float*)d_out;

    cudaFuncSetAttribute(persist, cudaFuncAttributeMaxDynamicSharedMemorySize, SMEM_BYTES);

    int sms = 0, occ = 0;
    cudaDeviceGetAttribute(&sms, cudaDevAttrMultiProcessorCount, 0);
    cudaOccupancyMaxActiveBlocksPerMultiprocessor(&occ, persist, 256, SMEM_BYTES);
    if (occ < 1) occ = 1;
    int G = occ * sms;
    if (G > 297) G = 297;
    if (G < 2) G = 2;

    prologue_kernel<<<XTOT / 256, 256>>>(x, Wf, bf, Wi, bi, Wo, bo, Wg, bg);
    persist<<<G, 256, SMEM_BYTES>>>(out);
}

// round 16
// speedup vs baseline: 1.0237x; 1.0237x over previous
#include <cuda_runtime.h>
#include <cuda_fp16.h>
#include <cstdint>
#include <math.h>

#define T_LEN 256
#define B_DIM 512
#define F_DIM 256
#define H_DIM 512
#define P_INT 12
#define KTOT  768
#define NG    2048
#define NW    22
#define XTOT  (T_LEN * B_DIM * F_DIM)

// ---------------- GEMM tiling ----------------
#define BM 128
#define BN 128
#define BK 64
#define STG 3
#define NCH (KTOT / BK)

#define A_SZ (BM * BK * 2)
#define B_SZ (BN * BK * 2)
#define SMEM_BYTES (STG * (A_SZ + B_SZ))  // 96 KB

#define WAVE_ROWS (P_INT * B_DIM)
#define WAVE_S ((size_t)WAVE_ROWS * NG)
#define NMT_MAX 48

// tasks: 21 full waves (768 gemm + 768 pw = 1536); pruned last wave: 112 gemm + 64 pw
#define FULL_TASKS (21 * 1536)
#define LAST_GEMM 112
#define LAST_TASKS (LAST_GEMM + 64)
#define TOTAL_TASKS (FULL_TASKS + LAST_TASKS)

__device__ __constant__ int c_lastmt[7] = {0, 4, 8, 12, 13, 14, 15};

// ---------------- static device scratch ----------------
__device__ __half d_Wh[NG * KTOT];
__device__ float  d_Bcat[NG];
__device__ __half d_Xh[XTOT];
__device__ __half d_Hh[P_INT * B_DIM * H_DIM];
__device__ __half d_Sbuf[2 * WAVE_S];
__device__ float  d_Vbuf[2 * P_INT * H_DIM];
__device__ int    d_gemmdone[NMT_MAX];
__device__ int    d_pwdone[NMT_MAX];
__device__ int    d_vflag[P_INT];
__device__ int    d_qhead;

// ---------------- helpers ----------------
__device__ __forceinline__ uint32_t smem_u32(const void* p) {
    uint32_t a;
    asm("{ .reg .u64 t; cvta.to.shared.u64 t, %1; cvt.u32.u64 %0, t; }" : "=r"(a) : "l"(p));
    return a;
}
__device__ __forceinline__ void cpasync16(uint32_t dst, const void* src) {
    asm volatile("cp.async.cg.shared.global [%0], [%1], 16;"
                 :: "r"(dst), "l"(__cvta_generic_to_global(src)) : "memory");
}
__device__ __forceinline__ void ldm4(uint32_t* r, uint32_t addr) {
    asm volatile("ldmatrix.sync.aligned.m8n8.x4.shared.b16 {%0,%1,%2,%3}, [%4];"
                 : "=r"(r[0]), "=r"(r[1]), "=r"(r[2]), "=r"(r[3]) : "r"(addr));
}
__device__ __forceinline__ void mma16816(float* d, const uint32_t* a, uint32_t b0, uint32_t b1) {
    asm volatile(
        "mma.sync.aligned.m16n8k16.row.col.f32.f16.f16.f32 "
        "{%0,%1,%2,%3}, {%4,%5,%6,%7}, {%8,%9}, {%0,%1,%2,%3};"
        : "+f"(d[0]), "+f"(d[1]), "+f"(d[2]), "+f"(d[3])
        : "r"(a[0]), "r"(a[1]), "r"(a[2]), "r"(a[3]), "r"(b0), "r"(b1));
}
__device__ __forceinline__ int ld_acq(const int* p) {
    int v;
    asm volatile("ld.acquire.gpu.s32 %0, [%1];" : "=r"(v) : "l"(p) : "memory");
    return v;
}
__device__ __forceinline__ void spin_hot(const int* p, int tgt) {
    while (ld_acq(p) < tgt) { }
}
__device__ __forceinline__ void spin_bk(const int* p, int tgt) {
    if (ld_acq(p) >= tgt) return;
    while (ld_acq(p) < tgt) __nanosleep(64);
}
__device__ __forceinline__ void done_release(int* p) {
    asm volatile("red.release.gpu.global.add.s32 [%0], %1;"
                 :: "l"(__cvta_generic_to_global(p)), "r"(1) : "memory");
}
__device__ __forceinline__ float tanh_fast(float x) {
    float y;
    asm("tanh.approx.f32 %0, %1;" : "=f"(y) : "f"(x));
    return y;
}

// ---------------- fused prologue: convert x, pack W/b, init state ----------------
__global__ void prologue_kernel(const float* __restrict__ x,
                                const float* __restrict__ Wf, const float* __restrict__ bf,
                                const float* __restrict__ Wi, const float* __restrict__ bi,
                                const float* __restrict__ Wo, const float* __restrict__ bo,
                                const float* __restrict__ Wg, const float* __restrict__ bg) {
    int idx = blockIdx.x * blockDim.x + threadIdx.x;
    d_Xh[idx] = __float2half(x[idx]);                     // grid sized to XTOT
    if (idx < NG * KTOT) {
        int n = idx / KTOT;
        int k = idx % KTOT;
        int g = n >> 9, h = n & 511;
        const float* W = (g == 0) ? Wf : (g == 1) ? Wi : (g == 2) ? Wo : Wg;
        d_Wh[idx] = __float2half(W[k * H_DIM + h]);
    }
    if (idx < NG) {
        int g = idx / H_DIM, h = idx % H_DIM;
        const float* bb = (g == 0) ? bf : (g == 1) ? bi : (g == 2) ? bo : bg;
        d_Bcat[idx] = bb[h];
    }
    if (idx < P_INT * B_DIM * H_DIM) d_Hh[idx] = __float2half(0.0f);
    if (idx < NMT_MAX) { d_gemmdone[idx] = 0; d_pwdone[idx] = 0; }
    if (idx < P_INT) d_vflag[idx] = 0;
    if (idx == 0) d_qhead = 0;
}

// ---------------- stage loader ----------------
__device__ __forceinline__ void load_stage(uint32_t sa, uint32_t sbB, int tid, int ch,
                                           const __half* Xb, const __half* Hb, const __half* Wb) {
    const int k0 = ch * BK;
    const __half* asrc;
    int astride;
    if (k0 < F_DIM) { asrc = Xb + k0;           astride = F_DIM; }
    else            { asrc = Hb + (k0 - F_DIM); astride = H_DIM; }
    #pragma unroll
    for (int i = 0; i < 4; i++) {
        int cell = tid + i * 256;
        int r = cell >> 3, c = cell & 7;
        cpasync16(sa + r * 128 + ((c ^ (r & 7)) * 16),
                  asrc + (size_t)r * astride + c * 8);
    }
    #pragma unroll
    for (int i = 0; i < 4; i++) {
        int cell = tid + i * 256;
        int r = cell >> 3, c = cell & 7;
        cpasync16(sbB + r * 128 + ((c ^ (r & 7)) * 16),
                  Wb + (size_t)r * KTOT + k0 + c * 8);
    }
}

// ---------------- warp softmax over 512 values (16 per lane) ----------------
__device__ __forceinline__ void softmax16(float* s) {
    float mx = -1e30f;
    #pragma unroll
    for (int q = 0; q < 16; q++) mx = fmaxf(mx, s[q]);
    #pragma unroll
    for (int o = 16; o > 0; o >>= 1) mx = fmaxf(mx, __shfl_xor_sync(0xffffffffu, mx, o));
    float sum = 0.0f;
    #pragma unroll
    for (int q = 0; q < 16; q++) { s[q] = __expf(s[q] - mx); sum += s[q]; }
    #pragma unroll
    for (int o = 16; o > 0; o >>= 1) sum += __shfl_xor_sync(0xffffffffu, sum, o);
    const float inv = 1.0f / sum;
    #pragma unroll
    for (int q = 0; q < 16; q++) s[q] *= inv;
}
// element q of lane l <-> column (q>>1)*64 + l*2 + (q&1)
__device__ __forceinline__ void load_gate16(const __half2* base, int l, float* s) {
    #pragma unroll
    for (int q2 = 0; q2 < 8; q2++) {
        float2 v = __half22float2(base[q2 * 32 + l]);
        s[2 * q2] = v.x;
        s[2 * q2 + 1] = v.y;
    }
}

// ---------------- persistent fused kernel ----------------
__global__ void __launch_bounds__(256, 2) persist(float* __restrict__ out) {
    extern __shared__ char smem[];
    const int G = gridDim.x;
    const int tid = threadIdx.x;

    if ((int)blockIdx.x == G - 1) {
        // ===== chain CTA: one warp, register-resident v across ALL waves =====
        if (tid >= 32) return;
        const int l = tid;
        float v[16];
        #pragma unroll
        for (int q = 0; q < 16; q++) v[q] = 0.0f;

        for (int w = 0; w < NW; w++) {
            const int t0 = w * P_INT;
            const int ns = (T_LEN - t0 < P_INT) ? (T_LEN - t0) : P_INT;
            const __half2* Sb2 = (const __half2*)(d_Sbuf + (size_t)(w & 1) * WAVE_S);
            float* Vb = d_Vbuf + (w & 1) * P_INT * H_DIM;
            for (int j = 0; j < ns; j++) {
                if (w >= 2 && l < 4) spin_hot(&d_pwdone[4 * j + l], 16 * (w - 1));
                __syncwarp();
                #pragma unroll
                for (int q2 = 0; q2 < 8; q2++)
                    *(float2*)(Vb + j * H_DIM + q2 * 64 + l * 2) =
                        make_float2(v[2 * q2], v[2 * q2 + 1]);
                __threadfence();
                __syncwarp();
                if (l == 0)
                    asm volatile("st.release.gpu.s32 [%0], %1;"
                                 :: "l"(d_vflag + j), "r"(w + 1) : "memory");
                spin_hot(&d_gemmdone[4 * j], 16 * (w + 1));
                const int r = (t0 + j + 1) % P_INT;
                const __half2* S = Sb2 + (((size_t)(j * B_DIM + r) * NG) >> 1);
                float sf[16], si[16], sg[16];
                load_gate16(S, l, sf);
                load_gate16(S + (H_DIM >> 1), l, si);
                load_gate16(S + ((3 * H_DIM) >> 1), l, sg);
                softmax16(sf);
                softmax16(si);
                #pragma unroll
                for (int q = 0; q < 16; q++)
                    v[q] = tanh_fast(sf[q] * v[q] + si[q] * tanh_fast(sg[q]));
            }
        }
        return;
    }

    // ===== worker CTA: global task queue =====
    __shared__ int s_task;
    const uint32_t sb = smem_u32(smem);
    const int wid = tid >> 5;
    const int l   = tid & 31;
    const int wm = (wid >> 2) * 64;
    const int wn = (wid & 3) * 32;
    const int lrow = l & 15;
    const int lk   = l >> 4;

    uint32_t sA[STG], sBs[STG];
    #pragma unroll
    for (int s = 0; s < STG; s++) {
        sA[s]  = sb + s * (A_SZ + B_SZ);
        sBs[s] = sA[s] + A_SZ;
    }

    while (true) {
        __syncthreads();
        if (tid == 0) s_task = atomicAdd(&d_qhead, 1);
        __syncthreads();
        const int task = s_task;
        if (task >= TOTAL_TASKS) break;

        int w, r, ns, ntile;
        bool is_gemm;
        int mtile = 0, n0 = 0, pwb = 0;
        if (task < FULL_TASKS) {
            w = task / 1536; r = task % 1536; ns = 12; ntile = 768;
            if (r < ntile) {
                is_gemm = true;
                const int grp = ns * 16;
                mtile = ((r % grp) >> 4) * 4 + r / grp;
                n0 = (r & 15) * BN;
            } else {
                is_gemm = false;
                pwb = r - ntile;
            }
        } else {
            w = 21; r = task - FULL_TASKS; ns = 4;
            if (r < LAST_GEMM) {
                is_gemm = true;
                mtile = c_lastmt[r >> 4];
                n0 = (r & 15) * BN;
            } else {
                is_gemm = false;
                pwb = 192 + (r - LAST_GEMM);   // only j==3 blocks
            }
        }
        const int t0 = w * P_INT;
        __half* Sb = d_Sbuf + (size_t)(w & 1) * WAVE_S;

        if (is_gemm) {
            const int m0 = mtile * BM;
            const __half* Xb = d_Xh + ((size_t)t0 * B_DIM + m0) * F_DIM;
            const __half* Hb = d_Hh + (size_t)m0 * H_DIM;
            const __half* Wb = d_Wh + (size_t)n0 * KTOT;

            // wave 0: h ring is all zeros -> skip K-chunks 4..11 (exact)
            const int nch_t = (w == 0) ? 4 : NCH;

            float acc[4][4][4];
            #pragma unroll
            for (int i = 0; i < 4; i++)
                #pragma unroll
                for (int j = 0; j < 4; j++)
                    #pragma unroll
                    for (int q = 0; q < 4; q++) acc[i][j][q] = 0.0f;

            #pragma unroll
            for (int c = 0; c < STG - 1; c++) {
                load_stage(sA[c], sBs[c], tid, c, Xb, Hb, Wb);
                asm volatile("cp.async.commit_group;" ::: "memory");
            }

            for (int ch = 0; ch < nch_t; ch++) {
                asm volatile("cp.async.wait_group 1;" ::: "memory");
                __syncthreads();
                const int cl = ch + STG - 1;
                if (cl == 4)
                    spin_bk(&d_pwdone[mtile], 16 * w);
                if (cl < nch_t)
                    load_stage(sA[cl % STG], sBs[cl % STG], tid, cl, Xb, Hb, Wb);
                asm volatile("cp.async.commit_group;" ::: "memory");

                const int s = ch % STG;
                #pragma unroll
                for (int kk = 0; kk < BK / 16; kk++) {
                    uint32_t af[4][4], bfr[2][4];
                    #pragma unroll
                    for (int mi = 0; mi < 4; mi++) {
                        int rr = wm + mi * 16 + lrow;
                        int cc = kk * 2 + lk;
                        ldm4(af[mi], sA[s] + rr * 128 + ((cc ^ (rr & 7)) * 16));
                    }
                    #pragma unroll
                    for (int bj = 0; bj < 2; bj++) {
                        int rr = wn + bj * 16 + lrow;
                        int cc = kk * 2 + lk;
                        ldm4(bfr[bj], sBs[s] + rr * 128 + ((cc ^ (rr & 7)) * 16));
                    }
                    #pragma unroll
                    for (int mi = 0; mi < 4; mi++)
                        #pragma unroll
                        for (int nj = 0; nj < 4; nj++)
                            mma16816(acc[mi][nj], af[mi],
                                     bfr[nj >> 1][nj & 1], bfr[nj >> 1][(nj & 1) + 2]);
                }
            }

            __half2* S2 = (__half2*)Sb;
            #pragma unroll
            for (int mi = 0; mi < 4; mi++) {
                #pragma unroll
                for (int nj = 0; nj < 4; nj++) {
                    int m = m0 + wm + mi * 16 + (l >> 2);
                    int n = n0 + wn + nj * 8 + (l & 3) * 2;
                    float b0 = d_Bcat[n], b1 = d_Bcat[n + 1];
                    S2[((size_t)m * NG + n) >> 1] =
                        __floats2half2_rn(acc[mi][nj][0] + b0, acc[mi][nj][1] + b1);
                    S2[((size_t)(m + 8) * NG + n) >> 1] =
                        __floats2half2_rn(acc[mi][nj][2] + b0, acc[mi][nj][3] + b1);
                }
            }
            __syncthreads();
            if (tid == 0) done_release(&d_gemmdone[mtile]);
        } else {
            // ---- pointwise block: 8 rows, warp per row ----
            const int b = pwb;
            const int mt = b >> 4;
            const int j  = b >> 6;
            if (tid == 0) spin_bk(&d_gemmdone[mt], 16 * (w + 1));
            __syncthreads();

            const int m = b * 8 + wid;
            const float* Vb = d_Vbuf + (w & 1) * P_INT * H_DIM;
            const __half2* S = (const __half2*)Sb + (((size_t)m * NG) >> 1);
            float sf[16], si[16], so[16], sg[16];
            load_gate16(S, l, sf);
            load_gate16(S + (H_DIM >> 1), l, si);
            load_gate16(S + ((2 * H_DIM) >> 1), l, so);
            load_gate16(S + ((3 * H_DIM) >> 1), l, sg);
            softmax16(sf);
            softmax16(si);
            softmax16(so);

            if (tid == 0) spin_bk(&d_vflag[j], w + 1);
            __syncthreads();

            __half2* Hh2 = (__half2*)d_Hh;
            const bool wout = (j == 3);
            #pragma unroll
            for (int q2 = 0; q2 < 8; q2++) {
                float2 vv = *(const float2*)(Vb + j * H_DIM + q2 * 64 + l * 2);
                float c0 = tanh_fast(sf[2 * q2] * vv.x + si[2 * q2] * tanh_fast(sg[2 * q2]));
                float c1 = tanh_fast(sf[2 * q2 + 1] * vv.y + si[2 * q2 + 1] * tanh_fast(sg[2 * q2 + 1]));
                float h0 = so[2 * q2] * c0;
                float h1 = so[2 * q2 + 1] * c1;
                Hh2[((size_t)m * H_DIM + q2 * 64 + l * 2) >> 1] = __floats2half2_rn(h0, h1);
                if (wout)
                    *(float2*)(out + (size_t)(m & 511) * H_DIM + q2 * 64 + l * 2) =
                        make_float2(h0, h1);
            }
            __syncthreads();
            if (tid == 0) done_release(&d_pwdone[mt]);
        }
    }
}

// ---------------- launch ----------------
extern "C" void kernel_launch(void* const* d_in, const int* in_sizes, int n_in,
                              void* d_out, int out_size) {
    const float* x  = (const float*)d_in[0];
    const float* Wf = (const float*)d_in[1];
    const float* bf = (const float*)d_in[2];
    const float* Wi = (const float*)d_in[3];
    const float* bi = (const float*)d_in[4];
    const float* Wo = (const float*)d_in[5];
    const float* bo = (const float*)d_in[6];
    const float* Wg = (const float*)d_in[7];
    const float* bg = (const float*)d_in[8];
    float* out = (float*)d_out;

    cudaFuncSetAttribute(persist, cudaFuncAttributeMaxDynamicSharedMemorySize, SMEM_BYTES);

    int sms = 0, occ = 0;
    cudaDeviceGetAttribute(&sms, cudaDevAttrMultiProcessorCount, 0);
    cudaOccupancyMaxActiveBlocksPerMultiprocessor(&occ, persist, 256, SMEM_BYTES);
    if (occ < 1) occ = 1;
    int G = occ * sms;
    if (G > 297) G = 297;
    if (G < 2) G = 2;

    prologue_kernel<<<XTOT / 256, 256>>>(x, Wf, bf, Wi, bi, Wo, bo, Wg, bg);
    persist<<<G, 256, SMEM_BYTES>>>(out);
}